// round 3
// baseline (speedup 1.0000x reference)
#include <cuda_runtime.h>
#include <cuda_bf16.h>
#include <mma.h>
#include <cstdint>
#include <cstddef>

using namespace nvcuda;

#define BB 16
#define CCH 256
#define HH 56
#define WW 56
#define XT_H 58
#define XT_W 66

#define XS_LD 264                       // padded channel stride (elements)
#define XS_ELEMS (4 * 66 * XS_LD)       // 69696 bf16
#define XS_BYTES (XS_ELEMS * 2)         // 139392 B
#define WS_STAGE (16 * XS_LD)           // one weight stage, elements
#define SMEM_TOTAL (XS_BYTES + 2 * WS_STAGE * 2)   // 156288 B

#define N_KSTEPS 144                    // 9 taps * 16 channel-chunks
#define N_CTAS 448                      // 16 batches * 28 two-row strips

// ---------------- device-global scratch (allocation-free) ----------------
__device__ __nv_bfloat16 g_xt[BB * XT_H * XT_W * CCH];   // padded channels-last x (~31 MB)
__device__ __nv_bfloat16 g_wt[9 * CCH * CCH];            // conv0 weights [tap][c][o]
__device__ float g_fsum[BB * CCH];                       // spatial sums of relu(conv)
__device__ float g_c1t[CCH * CCH];                       // center taps, [c][o]
__device__ float g_c2t[CCH * CCH];
__device__ float g_c3t[CCH * CCH];
__device__ float g_c4t[CCH * CCH];
__device__ float g_fc1t[CCH * CCH];
__device__ float g_w1t[CCH * 64];
__device__ float g_w2c[64];

// ---------------- cp.async helpers ----------------
__device__ __forceinline__ void cp16(void* dst_smem, const void* src_gmem) {
    unsigned int d = (unsigned int)__cvta_generic_to_shared(dst_smem);
    asm volatile("cp.async.cg.shared.global [%0], [%1], 16;\n" :: "r"(d), "l"(src_gmem) : "memory");
}
__device__ __forceinline__ void cp_commit() { asm volatile("cp.async.commit_group;\n" ::: "memory"); }
__device__ __forceinline__ void cp_wait0()  { asm volatile("cp.async.wait_group 0;\n" ::: "memory"); }

// ---------------- pre-pass kernels ----------------
__global__ void k_zero_xt() {
    size_t i = (size_t)blockIdx.x * 256 + threadIdx.x;      // one uint4 = 8 bf16
    size_t n = (size_t)BB * XT_H * XT_W * CCH / 8;
    if (i < n) ((uint4*)g_xt)[i] = make_uint4(0, 0, 0, 0);
}

__global__ void k_zero_fsum() {
    g_fsum[blockIdx.x * 256 + threadIdx.x] = 0.f;
}

// NCHW fp32 -> padded [b][h+1][w+1][c] bf16 (32x32 smem transpose tiles)
__global__ void k_tr(const float* __restrict__ x) {
    __shared__ float tile[32][33];
    int wt = blockIdx.x;                // 0..1
    int h  = blockIdx.y;                // 0..55
    int z  = blockIdx.z;                // b*8 + cblock
    int b = z >> 3, ct = z & 7;
    int tx = threadIdx.x, ty = threadIdx.y;
    int c0 = ct * 32, w0 = wt * 32;
#pragma unroll
    for (int i = 0; i < 4; i++) {
        int c = c0 + ty + i * 8, w = w0 + tx;
        if (w < WW) tile[ty + i * 8][tx] = x[(((size_t)b * CCH + c) * HH + h) * WW + w];
    }
    __syncthreads();
#pragma unroll
    for (int i = 0; i < 4; i++) {
        int w = w0 + ty + i * 8, c = c0 + tx;
        if (w < WW)
            g_xt[(((size_t)b * XT_H + h + 1) * XT_W + (w + 1)) * CCH + c] =
                __float2bfloat16(tile[tx][ty + i * 8]);
    }
}

// conv0 weights [o][c][3][3] fp32 -> [tap][c][o] bf16
__global__ void k_wt(const float* __restrict__ w0) {
    int idx = blockIdx.x * 256 + threadIdx.x;
    if (idx >= 9 * CCH * CCH) return;
    int o = idx & 255, c = (idx >> 8) & 255, tap = idx >> 16;
    g_wt[idx] = __float2bfloat16(w0[(o * CCH + c) * 9 + tap]);
}

// center taps + fc1, transposed to [c][o]
__global__ void k_cent(const float* __restrict__ w01, const float* __restrict__ w02,
                       const float* __restrict__ w03, const float* __restrict__ w04,
                       const float* __restrict__ fc1, const float* __restrict__ w1,
                       const float* __restrict__ w2) {
    int idx = blockIdx.x * 256 + threadIdx.x;   // < 65536
    int o = idx & 255, c = idx >> 8;
    g_c1t[c * 256 + o]  = w01[(o * 256 + c) * 9 + 4];
    g_c2t[c * 256 + o]  = w02[(o * 256 + c) * 9 + 4];
    g_c3t[c * 256 + o]  = w03[(o * 256 + c) * 9 + 4];
    g_c4t[c * 256 + o]  = w04[(o * 256 + c) * 9 + 4];
    g_fc1t[c * 256 + o] = fc1[o * 256 + c];
    if (o < 64) g_w1t[c * 64 + o] = w1[(o * 256 + c) * 9 + 4];
    if (idx < 64) g_w2c[idx] = w2[idx * 9 + 4];
}

// ---------------- fused conv3x3 + bias + relu + spatial-sum (bf16 WMMA) ----------------
__global__ void __launch_bounds__(256, 1) k_conv(const float* __restrict__ bias0) {
    extern __shared__ __align__(16) unsigned char sraw[];
    __nv_bfloat16* xs  = (__nv_bfloat16*)sraw;               // [4][66][264]
    __nv_bfloat16* wsm = (__nv_bfloat16*)(sraw + XS_BYTES);  // 2 x [16][264]

    int tid = threadIdx.x, wid = tid >> 5;
    int b = blockIdx.x / 28;
    int h0 = (blockIdx.x % 28) * 2;

    // stage x tile: rows h0-1..h0+2 (xt rows h0..h0+3), cols -1..64 (xt cols 0..65)
    for (int i = tid; i < 4 * 66 * 32; i += 256) {
        int k8 = i & 31;
        int col = (i >> 5) % 66;
        int r = i / (66 * 32);
        const __nv_bfloat16* src = g_xt + ((((size_t)b * XT_H + h0 + r) * XT_W + col) * CCH + k8 * 8);
        cp16(xs + (r * 66 + col) * XS_LD + k8 * 8, src);
    }
    cp_commit();

    // weight stage 0
    {
        for (int i = tid; i < 16 * 32; i += 256) {
            int k8 = i & 31, row = i >> 5;
            cp16(wsm + row * XS_LD + k8 * 8, g_wt + (size_t)row * 256 + k8 * 8);
        }
        cp_commit();
    }
    cp_wait0();
    __syncthreads();

    // warp tiling: 4 warps over M (32 each of 128), 2 over N (128 each of 256)
    int warpM = wid & 3, warpN = wid >> 2;
    int rowl  = warpM >> 1;               // local image row 0/1
    int colb0 = (warpM & 1) * 32;         // local col base
    int n0    = warpN * 128;

    wmma::fragment<wmma::accumulator, 16, 16, 16, float> acc[2][8];
#pragma unroll
    for (int i = 0; i < 2; i++)
#pragma unroll
        for (int j = 0; j < 8; j++) wmma::fill_fragment(acc[i][j], 0.f);

    for (int ks = 0; ks < N_KSTEPS; ks++) {
        int buf = ks & 1;
        if (ks + 1 < N_KSTEPS) {
            int ks2 = ks + 1;
            int tap2 = ks2 >> 4, c02 = (ks2 & 15) << 4;
            for (int i = tid; i < 16 * 32; i += 256) {
                int k8 = i & 31, row = i >> 5;
                cp16(wsm + (buf ^ 1) * WS_STAGE + row * XS_LD + k8 * 8,
                     g_wt + ((size_t)tap2 * 256 + c02 + row) * 256 + k8 * 8);
            }
            cp_commit();
        }

        int tap = ks >> 4;
        int kh = tap / 3, kw = tap - kh * 3;
        int c0ch = (ks & 15) << 4;

        wmma::fragment<wmma::matrix_a, 16, 16, 16, __nv_bfloat16, wmma::row_major> a0, a1;
        const __nv_bfloat16* abase = xs + ((rowl + kh) * 66 + colb0 + kw) * XS_LD + c0ch;
        wmma::load_matrix_sync(a0, abase, XS_LD);
        wmma::load_matrix_sync(a1, abase + 16 * XS_LD, XS_LD);

        const __nv_bfloat16* bbase = wsm + buf * WS_STAGE + n0;
#pragma unroll
        for (int j = 0; j < 8; j++) {
            wmma::fragment<wmma::matrix_b, 16, 16, 16, __nv_bfloat16, wmma::row_major> bf;
            wmma::load_matrix_sync(bf, bbase + j * 16, XS_LD);
            wmma::mma_sync(acc[0][j], a0, bf, acc[0][j]);
            wmma::mma_sync(acc[1][j], a1, bf, acc[1][j]);
        }

        cp_wait0();
        __syncthreads();
    }

    // epilogue: dump tile [128 M][256 N] to smem (reuse xs region), reduce with bias+relu
    float* csm = (float*)sraw;            // [128][264] floats = 135168 B <= XS_BYTES
#pragma unroll
    for (int i = 0; i < 2; i++) {
        int m = rowl * 64 + colb0 + i * 16;
#pragma unroll
        for (int j = 0; j < 8; j++)
            wmma::store_matrix_sync(csm + (size_t)m * XS_LD + n0 + j * 16, acc[i][j],
                                    XS_LD, wmma::mem_row_major);
    }
    __syncthreads();

    int o = tid;
    float bo = bias0[o];
    float sum = 0.f;
#pragma unroll 4
    for (int m = 0; m < 128; m++) {
        int col = m & 63;
        if (col < WW) {
            float v = csm[(size_t)m * XS_LD + o] + bo;
            sum += fmaxf(v, 0.f);
        }
    }
    atomicAdd(&g_fsum[b * 256 + o], sum);
}

// ---------------- tail: all 1x1-spatial ops + CRF, one block per batch ----------------
__global__ void k_tail(const float* __restrict__ b0_1, const float* __restrict__ b0_2,
                       const float* __restrict__ b0_3, const float* __restrict__ b0_4,
                       const float* __restrict__ b1,   const float* __restrict__ b2,
                       const float* __restrict__ fc2w, const float* __restrict__ fc2b,
                       const float* __restrict__ compat, const float* __restrict__ sw,
                       float* __restrict__ out) {
    __shared__ float s_a[256], s_b[256], s_f3s[64], s_vs, s_red[256];
    int b = blockIdx.x, t = threadIdx.x;

    s_a[t] = g_fsum[b * 256 + t] * (1.f / 3136.f);   // f1c
    __syncthreads();

    // f2 = relu(c1t^T f1c + b0_1), vc = sigmoid(fc1 f1c)
    float a2 = 0.f, avc = 0.f;
    for (int c = 0; c < 256; c++) {
        float v = s_a[c];
        a2  += g_c1t[c * 256 + t] * v;
        avc += g_fc1t[c * 256 + t] * v;
    }
    float f2 = fmaxf(a2 + b0_1[t], 0.f);
    float vc = 1.f / (1.f + expf(-avc));
    s_b[t] = vc * f2;                                 // f_c
    __syncthreads();

    // f3
    float a3 = 0.f;
    for (int c = 0; c < 256; c++) a3 += g_c2t[c * 256 + t] * s_b[c];
    float f3 = fmaxf(a3 + b0_2[t], 0.f);
    __syncthreads();
    s_a[t] = f3;                                      // f3
    __syncthreads();

    // f4 (regs) and f3s (threads < 64)
    float a4 = 0.f;
    for (int c = 0; c < 256; c++) a4 += g_c3t[c * 256 + t] * s_a[c];
    float f4 = fmaxf(a4 + b0_3[t], 0.f);
    if (t < 64) {
        float as = 0.f;
        for (int c = 0; c < 256; c++) as += g_w1t[c * 64 + t] * s_a[c];
        s_f3s[t] = fmaxf(as + b1[t], 0.f);
    }
    __syncthreads();

    // v0s scalar + CRF (thread 0)
    if (t == 0) {
        float u = 0.f;
        for (int c = 0; c < 64; c++) u += g_w2c[c] * s_f3s[c];
        u = fmaxf(u + b2[0], 0.f);
        float c00 = compat[0], c01 = compat[1], c10 = compat[2], c11 = compat[3];
        float sw0 = sw[0], sw1 = sw[1];
        float m = fabsf(u);
        float e0 = expf(u - m), e1 = expf(-u - m);
        float q0 = e0 / (e0 + e1), q1 = e1 / (e0 + e1);
        for (int it = 0; it < 5; it++) {
            float m0 = 0.25f * q0 * sw0, m1 = 0.25f * q1 * sw1;
            float p0 = c00 * m0 + c01 * m1;
            float p1 = c10 * m0 + c11 * m1;
            float x0 = u - p0, x1 = -u - p1;
            float mm = fmaxf(x0, x1);
            float f0 = expf(x0 - mm), f1 = expf(x1 - mm);
            float s = f0 + f1;
            q0 = f0 / s; q1 = f1 / s;
        }
        s_vs = q1;
    }
    __syncthreads();

    // f_s = v_s * f4, then f_r
    s_b[t] = s_vs * f4;
    __syncthreads();
    float ar = 0.f;
    for (int c = 0; c < 256; c++) ar += g_c4t[c * 256 + t] * s_b[c];
    float fr = fmaxf(ar + b0_4[t], 0.f);

    // p = sigmoid(fc2 . f_r + fc2_b)
    s_red[t] = fc2w[t] * fr;
    __syncthreads();
    for (int s = 128; s > 0; s >>= 1) {
        if (t < s) s_red[t] += s_red[t + s];
        __syncthreads();
    }
    if (t == 0) out[b] = 1.f / (1.f + expf(-(s_red[0] + fc2b[0])));
}

// ---------------- launch ----------------
extern "C" void kernel_launch(void* const* d_in, const int* in_sizes, int n_in,
                              void* d_out, int out_size) {
    const float* x     = (const float*)d_in[0];
    const float* w0_0  = (const float*)d_in[1];
    const float* b0_0  = (const float*)d_in[2];
    const float* w0_1  = (const float*)d_in[3];
    const float* b0_1  = (const float*)d_in[4];
    const float* w0_2  = (const float*)d_in[5];
    const float* b0_2  = (const float*)d_in[6];
    const float* w0_3  = (const float*)d_in[7];
    const float* b0_3  = (const float*)d_in[8];
    const float* w0_4  = (const float*)d_in[9];
    const float* b0_4  = (const float*)d_in[10];
    const float* w1    = (const float*)d_in[11];
    const float* b1    = (const float*)d_in[12];
    const float* w2    = (const float*)d_in[13];
    const float* b2    = (const float*)d_in[14];
    const float* fc1w  = (const float*)d_in[15];
    const float* fc2w  = (const float*)d_in[16];
    const float* fc2b  = (const float*)d_in[17];
    const float* compat= (const float*)d_in[18];
    const float* sw    = (const float*)d_in[19];
    float* out = (float*)d_out;

    cudaFuncSetAttribute(k_conv, cudaFuncAttributeMaxDynamicSharedMemorySize, SMEM_TOTAL);

    size_t nxt8 = (size_t)BB * XT_H * XT_W * CCH / 8;
    k_zero_xt<<<(int)((nxt8 + 255) / 256), 256>>>();
    k_zero_fsum<<<16, 256>>>();
    k_tr<<<dim3(2, 56, 128), dim3(32, 8)>>>(x);
    k_wt<<<(9 * 256 * 256 + 255) / 256, 256>>>(w0_0);
    k_cent<<<256, 256>>>(w0_1, w0_2, w0_3, w0_4, fc1w, w1, w2);
    k_conv<<<N_CTAS, 256, SMEM_TOTAL>>>(b0_0);
    k_tail<<<16, 256>>>(b0_1, b0_2, b0_3, b0_4, b1, b2, fc2w, fc2b, compat, sw, out);
}